// round 2
// baseline (speedup 1.0000x reference)
#include <cuda_runtime.h>
#include <cstdint>

#define N_NODES 500000
#define HD      128
#define TM      128
#define THREADS 512
#define NTILES  ((N_NODES + TM - 1) / TM)   // 3907

// -------- SMEM layout (bytes, dynamic) --------
// A_x   [128 rows x 128 f32], 512B/row, xor-16 swizzle   (reused as i_n stash after pass 0)
// A_red [128 rows x 128 f32]
// B stages: 2 x (384 weight rows x 32 f32), 128B/row, xor-16 swizzle
#define OFF_AX    0
#define OFF_ARED  65536
#define OFF_B     131072
#define STAGE_B   49152
#define SMEM_BYTES 229376

static __device__ __forceinline__ uint32_t smem_u32(const void* p) {
    uint32_t a;
    asm("{ .reg .u64 t; cvta.to.shared.u64 t, %1; cvt.u32.u64 %0, t; }" : "=r"(a) : "l"(p));
    return a;
}
static __device__ __forceinline__ void cp16(uint32_t dst, const void* src) {
    asm volatile("cp.async.cg.shared.global [%0], [%1], 16;" :: "r"(dst), "l"(src));
}
static __device__ __forceinline__ void cp_commit() {
    asm volatile("cp.async.commit_group;" ::: "memory");
}
static __device__ __forceinline__ void cp_wait1() {
    asm volatile("cp.async.wait_group 1;" ::: "memory");
}
static __device__ __forceinline__ uint32_t f2tf(float f) {
    uint32_t u;
    asm("cvt.rna.tf32.f32 %0, %1;" : "=r"(u) : "f"(f));
    return u;
}
static __device__ __forceinline__ void mma8(float* c, const uint32_t* a,
                                            uint32_t b0, uint32_t b1) {
    asm volatile(
        "mma.sync.aligned.m16n8k8.row.col.f32.tf32.tf32.f32 "
        "{%0,%1,%2,%3}, {%4,%5,%6,%7}, {%8,%9}, {%0,%1,%2,%3};"
        : "+f"(c[0]), "+f"(c[1]), "+f"(c[2]), "+f"(c[3])
        : "r"(a[0]), "r"(a[1]), "r"(a[2]), "r"(a[3]), "r"(b0), "r"(b1));
}
static __device__ __forceinline__ float sigmoidf_(float v) {
    return __fdividef(1.0f, 1.0f + __expf(-v));
}
static __device__ __forceinline__ float tanhf_(float v) {
    return __fdividef(2.0f, 1.0f + __expf(-2.0f * v)) - 1.0f;
}
static __device__ __forceinline__ float lds_f(const char* smem, uint32_t off) {
    return *(const float*)(smem + off);
}

__global__ void __launch_bounds__(THREADS)
gru_gnn_kernel(const float* __restrict__ x, const float* __restrict__ h,
               const float* __restrict__ w_ih, const float* __restrict__ w_hh,
               const float* __restrict__ b_ih, const float* __restrict__ b_hh,
               const int* __restrict__ src, float* __restrict__ out) {
    extern __shared__ char smem[];
    uint32_t sb = smem_u32(smem);
    const int tid  = threadIdx.x;
    const int wid  = tid >> 5;
    const int lane = tid & 31;
    const int rg   = wid >> 2;     // row group: 32 rows
    const int g    = wid & 3;      // col group: 32 gate cols
    const int tq   = lane & 3;
    const int tg   = lane >> 2;
    const long m0  = (long)blockIdx.x * TM;

    // ---- Issue A tiles (x, red=h[src]) + B chunk 0 => group 0; B chunk 1 => group 1
    {
#pragma unroll
        for (int j = 0; j < 8; ++j) {
            int idx = tid + j * THREADS;          // 0..4095
            int r = idx >> 5, u = idx & 31;
            long row = m0 + r;
            if (row >= N_NODES) row = N_NODES - 1;
            uint32_t sw = (uint32_t)(r * 512 + ((u * 16) ^ ((r & 7) * 16)));
            cp16(sb + OFF_AX + sw, x + row * HD + u * 4);
            int srow = __ldg(src + row);
            cp16(sb + OFF_ARED + sw, h + (long)srow * HD + u * 4);
        }
#pragma unroll
        for (int j = 0; j < 6; ++j) {             // B chunk 0: w_ih K[0..32)
            int idx = tid + j * THREADS;          // 0..3071
            int n = idx >> 3, u8 = idx & 7;
            uint32_t sw = (uint32_t)(n * 128 + ((u8 * 16) ^ ((n & 7) * 16)));
            cp16(sb + OFF_B + sw, w_ih + n * HD + u8 * 4);
        }
        cp_commit();
#pragma unroll
        for (int j = 0; j < 6; ++j) {             // B chunk 1: w_ih K[32..64)
            int idx = tid + j * THREADS;
            int n = idx >> 3, u8 = idx & 7;
            uint32_t sw = (uint32_t)(n * 128 + ((u8 * 16) ^ ((n & 7) * 16)));
            cp16(sb + OFF_B + STAGE_B + sw, w_ih + n * HD + 32 + u8 * 4);
        }
        cp_commit();
    }

    float acc[96];   // [m(2)][nt(12)][q(4)]; nt 0-3 = r, 4-7 = z, 8-11 = n
#pragma unroll
    for (int i = 0; i < 96; ++i) acc[i] = 0.0f;

    const int r0 = rg * 32 + tg;                  // base row (m adds 16, hi-regs add 8)
    const uint32_t xa = (uint32_t)((r0 & 7) * 16);
    const uint32_t xb = (uint32_t)(tg * 16);
    // B weight-row bases per n-tile (all + tg)
    uint32_t brow[12];
#pragma unroll
    for (int nt = 0; nt < 12; ++nt) {
        int sec = (nt < 4) ? 0 : (nt < 8) ? 128 : 256;
        brow[nt] = (uint32_t)((sec + g * 32 + (nt & 3) * 8 + tg) * 128);
    }

#pragma unroll 1
    for (int c = 0; c < 8; ++c) {
        cp_wait1();
        __syncthreads();

        const int p = c >> 2;
        const char* As = smem + (p ? OFF_ARED : OFF_AX);
        const char* Bs = smem + OFF_B + (c & 1) * STAGE_B;
        const uint32_t ab0 = (uint32_t)(r0 * 512);

#pragma unroll
        for (int kt = 0; kt < 4; ++kt) {
            uint32_t kb  = (uint32_t)(((c & 3) * 32 + kt * 8 + tq) * 4);
            uint32_t ka  = kb ^ xa;
            uint32_t ka2 = (kb + 16) ^ xa;
            uint32_t kkb = (uint32_t)((kt * 8 + tq) * 4);
            uint32_t kB  = kkb ^ xb;
            uint32_t kB2 = (kkb + 16) ^ xb;

            uint32_t afr[2][4];
#pragma unroll
            for (int m = 0; m < 2; ++m) {
                uint32_t ab = ab0 + (uint32_t)(m * 16 * 512);
                afr[m][0] = f2tf(lds_f(As, ab + ka));
                afr[m][1] = f2tf(lds_f(As, ab + 8 * 512 + ka));
                afr[m][2] = f2tf(lds_f(As, ab + ka2));
                afr[m][3] = f2tf(lds_f(As, ab + 8 * 512 + ka2));
            }
#pragma unroll
            for (int nt = 0; nt < 12; ++nt) {
                uint32_t b0 = f2tf(lds_f(Bs, brow[nt] + kB));
                uint32_t b1 = f2tf(lds_f(Bs, brow[nt] + kB2));
                mma8(&acc[(0 * 12 + nt) * 4], afr[0], b0, b1);
                mma8(&acc[(1 * 12 + nt) * 4], afr[1], b0, b1);
            }
        }

        __syncthreads();                          // stage (c&1) free to refill
        if (c + 2 < 8) {
            const float* wsrc = ((c + 2) >> 2) ? w_hh : w_ih;
            int k0 = ((c + 2) & 3) * 32;
            uint32_t stb = OFF_B + (uint32_t)((c & 1) * STAGE_B);
#pragma unroll
            for (int j = 0; j < 6; ++j) {
                int idx = tid + j * THREADS;
                int n = idx >> 3, u8 = idx & 7;
                uint32_t sw = (uint32_t)(n * 128 + ((u8 * 16) ^ ((n & 7) * 16)));
                cp16(sb + stb + sw, wsrc + n * HD + k0 + u8 * 4);
            }
        }
        cp_commit();

        if (c == 3) {
            // pass 0 done: stash i_n into (dead) A_x region, zero n accumulators
            float* st = (float*)(smem + OFF_AX) + wid * 1024 + lane;
#pragma unroll
            for (int m = 0; m < 2; ++m)
#pragma unroll
                for (int nt = 8; nt < 12; ++nt)
#pragma unroll
                    for (int q = 0; q < 4; ++q) {
                        int e = (m * 4 + (nt - 8)) * 4 + q;
                        st[e * 32] = acc[(m * 12 + nt) * 4 + q];
                        acc[(m * 12 + nt) * 4 + q] = 0.0f;
                    }
        }
    }

    // ---- Epilogue: all gate values for (row, j) are thread-local
    const float* st = (const float*)(smem + OFF_AX) + wid * 1024 + lane;
#pragma unroll
    for (int m = 0; m < 2; ++m) {
#pragma unroll
        for (int nt = 0; nt < 4; ++nt) {
#pragma unroll
            for (int qr = 0; qr < 2; ++qr) {
                int rowl = rg * 32 + m * 16 + tg + qr * 8;
                long grow = m0 + rowl;
                int jb = g * 32 + nt * 8 + tq * 2;
                float2 o;
#pragma unroll
                for (int jq = 0; jq < 2; ++jq) {
                    int q = qr * 2 + jq;
                    int j = jb + jq;
                    float rr = acc[(m * 12 + nt) * 4 + q]
                             + __ldg(b_ih + j) + __ldg(b_hh + j);
                    float zz = acc[(m * 12 + nt + 4) * 4 + q]
                             + __ldg(b_ih + 128 + j) + __ldg(b_hh + 128 + j);
                    float hn = acc[(m * 12 + nt + 8) * 4 + q] + __ldg(b_hh + 256 + j);
                    int e = (m * 4 + nt) * 4 + q;
                    float inq = st[e * 32] + __ldg(b_ih + 256 + j);
                    float rgate = sigmoidf_(rr);
                    float zgate = sigmoidf_(zz);
                    float ngate = tanhf_(inq + rgate * hn);
                    float red = lds_f(smem + OFF_ARED,
                                      (uint32_t)(rowl * 512 + ((j * 4) ^ ((rowl & 7) * 16))));
                    (&o.x)[jq] = (1.0f - zgate) * ngate + zgate * red;
                }
                if (grow < N_NODES)
                    *(float2*)(out + grow * HD + jb) = o;
            }
        }
    }
}

extern "C" void kernel_launch(void* const* d_in, const int* in_sizes, int n_in,
                              void* d_out, int out_size) {
    const float* x    = (const float*)d_in[0];
    const float* h    = (const float*)d_in[1];
    const float* w_ih = (const float*)d_in[2];
    const float* w_hh = (const float*)d_in[3];
    const float* b_ih = (const float*)d_in[4];
    const float* b_hh = (const float*)d_in[5];
    const int*   src  = (const int*)d_in[6];
    // d_in[7] = dst = arange(N): segment_sum collapses to a gather; unused.
    float* out = (float*)d_out;

    cudaFuncSetAttribute(gru_gnn_kernel, cudaFuncAttributeMaxDynamicSharedMemorySize,
                         SMEM_BYTES);
    gru_gnn_kernel<<<NTILES, THREADS, SMEM_BYTES>>>(x, h, w_ih, w_hh, b_ih, b_hh,
                                                    src, out);
}